// round 5
// baseline (speedup 1.0000x reference)
#include <cuda_runtime.h>
#include <cuda_bf16.h>
#include <cstdint>

#define NN   65536
#define SS   128
#define DIN  512
#define HH   1024
#define DOUTT 256

// ---------------- static device scratch ----------------
__device__ float g_u[NN];
__device__ float g_v2[HH];
__device__ float g_c;
__device__ float g_gram_part[128 * 128 * 128];
__device__ float g_y_part[512 * 128];
__device__ float g_G[128 * 128];
__device__ float g_y[128];
__device__ float g_wprime[128];

// ---------------- helpers (baseline PTX only — must compile for plain sm_103) ----------------
__device__ __forceinline__ uint32_t smem_u32(const void* p) {
    uint32_t a;
    asm("{ .reg .u64 t; cvta.to.shared.u64 t, %1; cvt.u32.u64 %0, t; }" : "=r"(a) : "l"(p));
    return a;
}
__device__ __forceinline__ void cp16(uint32_t dst, const void* src) {
    asm volatile("cp.async.cg.shared.global [%0], [%1], 16;" :: "r"(dst), "l"(src));
}
#define CP_COMMIT() asm volatile("cp.async.commit_group;" ::: "memory")
#define CP_WAIT0()  asm volatile("cp.async.wait_group 0;" ::: "memory")

__device__ __forceinline__ void mma_tf32(float* c, const uint32_t* a, const uint32_t* b) {
    asm volatile("mma.sync.aligned.m16n8k8.row.col.f32.tf32.tf32.f32 "
        "{%0,%1,%2,%3}, {%4,%5,%6,%7}, {%8,%9}, {%0,%1,%2,%3};"
        : "+f"(c[0]), "+f"(c[1]), "+f"(c[2]), "+f"(c[3])
        : "r"(a[0]), "r"(a[1]), "r"(a[2]), "r"(a[3]), "r"(b[0]), "r"(b[1]));
}
// fp32 bits fed directly as tf32 (HW ignores low mantissa bits -> truncation round)
__device__ __forceinline__ uint32_t asbits(float f) { return __float_as_uint(f); }

// ---------------- K1: v2 = W2 @ w_deep, c = b2 . w_deep ----------------
__global__ void k_prep(const float* __restrict__ W2,
                       const float* __restrict__ w_deep,
                       const float* __restrict__ b2) {
    int h = blockIdx.x * blockDim.x + threadIdx.x;
    if (h < HH) {
        float acc = 0.f;
        const float* row = W2 + (size_t)h * DOUTT;
#pragma unroll 8
        for (int d = 0; d < DOUTT; d++) acc = fmaf(row[d], w_deep[d], acc);
        g_v2[h] = acc;
    }
    if (blockIdx.x == 0 && threadIdx.x == 0) {
        float c = 0.f;
        for (int d = 0; d < DOUTT; d++) c = fmaf(b2[d], w_deep[d], c);
        g_c = c;
    }
}

// ---------------- K2: tf32 mma.sync MLP, fused u and y partials ----------------
// 512 threads = 16 warps (4m x 4n), warp tile 32x32, BM=128, BN=128,
// nc-loop over 8 chunks of 128 hidden cols, K=512 in 16 chunks of 32.
// SMEM float offsets (padded strides: A row = 36 floats, B row = 136 floats)
#define OFF_A0   0
#define OFF_A1   4608
#define OFF_B0   9216
#define OFF_B1   13568
#define OFF_B1S  17920
#define OFF_V2S  18944
#define OFF_RED  19968
#define OFF_US   22016
#define MLP_SMEM_BYTES ((22016 + 160) * 4)

__device__ __forceinline__ void mlp_load(uint32_t sb, uint32_t aoff, uint32_t boff,
                                         const float* __restrict__ d1,
                                         const float* __restrict__ W1,
                                         int mbase, int kbase, int nbase, int tid) {
    // A: 128 rows x 32 floats = 1024 16B chunks; B: 32 rows x 128 floats = 1024 chunks
#pragma unroll
    for (int c = 0; c < 2; c++) {
        int id = c * 512 + tid;
        int row = id >> 3, cc = id & 7;
        cp16(sb + (aoff + row * 36 + cc * 4) * 4,
             &d1[(size_t)(mbase + row) * DIN + kbase + cc * 4]);
    }
#pragma unroll
    for (int c = 0; c < 2; c++) {
        int id = c * 512 + tid;
        int row = id >> 5, cc = id & 31;
        cp16(sb + (boff + row * 136 + cc * 4) * 4,
             &W1[(size_t)(kbase + row) * HH + nbase + cc * 4]);
    }
}

__global__ __launch_bounds__(512)
void k_mlp(const float* __restrict__ d1, const float* __restrict__ W1,
           const float* __restrict__ b1, const float* __restrict__ S) {
    extern __shared__ float smf[];
    const uint32_t sb = smem_u32(smf);
    const int tid = threadIdx.x, wid = tid >> 5, lane = tid & 31;
    const int wm = wid >> 2, wn = wid & 3;       // warp grid 4 x 4
    const int mbase = blockIdx.x * 128;
    const int lq = lane >> 2, lr = lane & 3;

    float* b1s = smf + OFF_B1S;
    float* v2s = smf + OFF_V2S;
    for (int i = tid; i < HH; i += 512) { b1s[i] = b1[i]; v2s[i] = g_v2[i]; }
    __syncthreads();

    const uint32_t aoff[2] = {OFF_A0, OFF_A1};
    const uint32_t boff[2] = {OFF_B0, OFF_B1};
    float upart[4] = {0.f, 0.f, 0.f, 0.f};

    for (int nc = 0; nc < 8; nc++) {
        const int nbase = nc * 128;
        float c[2][4][4];
#pragma unroll
        for (int mt = 0; mt < 2; mt++)
#pragma unroll
            for (int nt = 0; nt < 4; nt++)
#pragma unroll
                for (int i = 0; i < 4; i++) c[mt][nt][i] = 0.f;

        mlp_load(sb, aoff[0], boff[0], d1, W1, mbase, 0, nbase, tid);
        CP_COMMIT();

        for (int kt = 0; kt < 16; kt++) {
            const int cur = kt & 1, nxt = cur ^ 1;
            CP_WAIT0();
            __syncthreads();
            if (kt < 15) {
                mlp_load(sb, aoff[nxt], boff[nxt], d1, W1, mbase, (kt + 1) * 32, nbase, tid);
                CP_COMMIT();
            }
            const float* As = smf + aoff[cur];
            const float* Bs = smf + boff[cur];
#pragma unroll
            for (int ks = 0; ks < 4; ks++) {
                const int k0 = ks * 8;
                uint32_t af[2][4];
#pragma unroll
                for (int mt = 0; mt < 2; mt++) {
                    const int rm = wm * 32 + mt * 16 + lq;
                    const float* ap = As + rm * 36 + k0 + lr;
                    af[mt][0] = asbits(ap[0]);
                    af[mt][1] = asbits(ap[8 * 36]);
                    af[mt][2] = asbits(ap[4]);
                    af[mt][3] = asbits(ap[8 * 36 + 4]);
                }
                uint32_t bf[4][2];
#pragma unroll
                for (int nt = 0; nt < 4; nt++) {
                    const int n = wn * 32 + nt * 8 + lq;
                    const float* bp = Bs + (k0 + lr) * 136 + n;
                    bf[nt][0] = asbits(bp[0]);
                    bf[nt][1] = asbits(bp[4 * 136]);
                }
#pragma unroll
                for (int mt = 0; mt < 2; mt++)
#pragma unroll
                    for (int nt = 0; nt < 4; nt++)
                        mma_tf32(c[mt][nt], af[mt], bf[nt]);
            }
        }
        // fused epilogue: upart += relu(c + b1) . v2
#pragma unroll
        for (int mt = 0; mt < 2; mt++)
#pragma unroll
            for (int nt = 0; nt < 4; nt++) {
                const int col0 = nbase + wn * 32 + nt * 8 + 2 * lr;
                const float b1a = b1s[col0], b1b = b1s[col0 + 1];
                const float v2a = v2s[col0], v2b = v2s[col0 + 1];
                upart[mt * 2 + 0] = fmaf(fmaxf(c[mt][nt][0] + b1a, 0.f), v2a, upart[mt * 2 + 0]);
                upart[mt * 2 + 0] = fmaf(fmaxf(c[mt][nt][1] + b1b, 0.f), v2b, upart[mt * 2 + 0]);
                upart[mt * 2 + 1] = fmaf(fmaxf(c[mt][nt][2] + b1a, 0.f), v2a, upart[mt * 2 + 1]);
                upart[mt * 2 + 1] = fmaf(fmaxf(c[mt][nt][3] + b1b, 0.f), v2b, upart[mt * 2 + 1]);
            }
        __syncthreads();  // before next nc overwrites buffers
    }

    // reduce 16 column-partials per row (deterministic), store u, then y partial
    float* red = smf + OFF_RED;   // [128][16]
    float* us  = smf + OFF_US;    // [128]
#pragma unroll
    for (int mt = 0; mt < 2; mt++)
#pragma unroll
        for (int hh = 0; hh < 2; hh++) {
            const int row = wm * 32 + mt * 16 + hh * 8 + lq;
            red[row * 16 + wn * 4 + lr] = upart[mt * 2 + hh];
        }
    __syncthreads();
    if (tid < 128) {
        float s = 0.f;
#pragma unroll
        for (int t = 0; t < 16; t++) s += red[tid * 16 + t];
        const float u = s + g_c;
        g_u[mbase + tid] = u;
        us[tid] = u;
    }
    __syncthreads();
    if (tid < 128) {
        float acc = 0.f;
#pragma unroll 8
        for (int r = 0; r < 128; r++)
            acc = fmaf(S[(size_t)(mbase + r) * SS + tid], us[r], acc);
        g_y_part[blockIdx.x * 128 + tid] = acc;
    }
}

// ---------------- K3: Gram partials (FFMA, known good) ----------------
__global__ __launch_bounds__(256) void k_gram(const float* __restrict__ Smat) {
    __shared__ __align__(16) float Srow[8][128];
    const int tid = threadIdx.x;
    const int tx = tid & 15, ty = tid >> 4;
    const int i0 = ty * 8, j0 = tx * 8;
    const int base = blockIdx.x * 512;
    const int lr = tid >> 5;
    const int lc = (tid & 31) * 4;

    float acc[8][8];
#pragma unroll
    for (int i = 0; i < 8; i++)
#pragma unroll
        for (int j = 0; j < 8; j++) acc[i][j] = 0.f;

    for (int st = 0; st < 64; st++) {
        __syncthreads();
        *(float4*)&Srow[lr][lc] = *(const float4*)&Smat[(size_t)(base + st * 8 + lr) * SS + lc];
        __syncthreads();
#pragma unroll
        for (int r = 0; r < 8; r++) {
            float a[8], b[8];
            *(float4*)&a[0] = *(float4*)&Srow[r][i0];
            *(float4*)&a[4] = *(float4*)&Srow[r][i0 + 4];
            *(float4*)&b[0] = *(float4*)&Srow[r][j0];
            *(float4*)&b[4] = *(float4*)&Srow[r][j0 + 4];
#pragma unroll
            for (int i = 0; i < 8; i++)
#pragma unroll
                for (int j = 0; j < 8; j++)
                    acc[i][j] = fmaf(a[i], b[j], acc[i][j]);
        }
    }
    float* outp = g_gram_part + (size_t)blockIdx.x * 128 * 128;
#pragma unroll
    for (int i = 0; i < 8; i++)
#pragma unroll
        for (int j = 0; j < 8; j++)
            outp[(i0 + i) * 128 + (j0 + j)] = acc[i][j];
}

// ---------------- K4: reduce partials (deterministic fixed order, MLP via unroll) ----------------
__global__ void k_reduce() {
    const int idx = blockIdx.x * blockDim.x + threadIdx.x;
    if (idx < 128 * 128) {
        float s = 0.f;
#pragma unroll 8
        for (int b = 0; b < 128; b++) s += g_gram_part[(size_t)b * 16384 + idx];
        g_G[idx] = s;
    }
    if (idx < 128) {
        float s = 0.f;
#pragma unroll 8
        for (int b = 0; b < 512; b++) s += g_y_part[b * 128 + idx];
        g_y[idx] = s;
    }
}

// ---------------- K5: Richardson solve G z = y ----------------
__global__ void k_solve(const float* __restrict__ w_struct) {
    __shared__ float zs[128];
    const int i = threadIdx.x;
    const float invN = 1.0f / (float)NN;
    const float yi = g_y[i];
    zs[i] = yi * invN;
    __syncthreads();
    for (int it = 0; it < 30; it++) {
        float gz = 0.f;
        const float* Gi = g_G + i * 128;
#pragma unroll 8
        for (int j = 0; j < 128; j++) gz = fmaf(Gi[j], zs[j], gz);
        const float znew = zs[i] + (yi - gz) * invN;
        __syncthreads();
        zs[i] = znew;
        __syncthreads();
    }
    g_wprime[i] = w_struct[i] - zs[i];
}

// ---------------- K6: out[n] = u[n] + S[n,:] . wprime (4 rows per warp) ----------------
__global__ __launch_bounds__(256) void k_final(const float* __restrict__ Smat,
                                               float* __restrict__ out) {
    __shared__ float wp[128];
    const int tid = threadIdx.x;
    if (tid < 128) wp[tid] = g_wprime[tid];
    __syncthreads();
    const int warp = tid >> 5, lane = tid & 31;
    const float4 w = *(const float4*)&wp[lane * 4];
#pragma unroll
    for (int r = 0; r < 4; r++) {
        const int row = blockIdx.x * 32 + warp * 4 + r;
        const float4 a = *(const float4*)&Smat[(size_t)row * SS + lane * 4];
        float s = a.x * w.x + a.y * w.y + a.z * w.z + a.w * w.w;
#pragma unroll
        for (int off = 16; off; off >>= 1) s += __shfl_xor_sync(0xffffffffu, s, off);
        if (lane == 0) out[row] = g_u[row] + s;
    }
}

// ---------------- launch ----------------
extern "C" void kernel_launch(void* const* d_in, const int* in_sizes, int n_in,
                              void* d_out, int out_size) {
    const float* structured = (const float*)d_in[0];
    const float* d1         = (const float*)d_in[1];
    const float* W1         = (const float*)d_in[2];
    const float* b1         = (const float*)d_in[3];
    const float* W2         = (const float*)d_in[4];
    const float* b2         = (const float*)d_in[5];
    const float* w_struct   = (const float*)d_in[6];
    const float* w_deep     = (const float*)d_in[7];
    float* out = (float*)d_out;
    (void)in_sizes; (void)n_in; (void)out_size;

    cudaFuncSetAttribute(k_mlp, cudaFuncAttributeMaxDynamicSharedMemorySize, MLP_SMEM_BYTES);

    k_prep  <<<4, 256>>>(W2, w_deep, b2);
    k_mlp   <<<NN / 128, 512, MLP_SMEM_BYTES>>>(d1, W1, b1, structured);
    k_gram  <<<128, 256>>>(structured);
    k_reduce<<<64, 256>>>();
    k_solve <<<1, 128>>>(w_struct);
    k_final <<<NN / 32, 256>>>(structured, out);
}

// round 6
// speedup vs baseline: 1.5906x; 1.5906x over previous
#include <cuda_runtime.h>
#include <cuda_bf16.h>
#include <cstdint>

#define NN   65536
#define SS   128
#define DIN  512
#define HH   1024
#define DOUTT 256

// ---------------- static device scratch ----------------
__device__ float g_u[NN];
__device__ float g_v2[HH];
__device__ float g_c;
__device__ float g_gram_part[128 * 128 * 128];
__device__ float g_y_part[512 * 128];
__device__ float g_G[128 * 128];
__device__ float g_y[128];
__device__ float g_wprime[128];

// ---------------- helpers (baseline PTX only — must compile for plain sm_103) ----------------
__device__ __forceinline__ uint32_t smem_u32(const void* p) {
    uint32_t a;
    asm("{ .reg .u64 t; cvta.to.shared.u64 t, %1; cvt.u32.u64 %0, t; }" : "=r"(a) : "l"(p));
    return a;
}
__device__ __forceinline__ void cp16(uint32_t dst, const void* src) {
    asm volatile("cp.async.cg.shared.global [%0], [%1], 16;" :: "r"(dst), "l"(src));
}
#define CP_COMMIT() asm volatile("cp.async.commit_group;" ::: "memory")
#define CP_WAIT0()  asm volatile("cp.async.wait_group 0;" ::: "memory")

__device__ __forceinline__ void mma_tf32(float* c, const uint32_t* a, const uint32_t* b) {
    asm volatile("mma.sync.aligned.m16n8k8.row.col.f32.tf32.tf32.f32 "
        "{%0,%1,%2,%3}, {%4,%5,%6,%7}, {%8,%9}, {%0,%1,%2,%3};"
        : "+f"(c[0]), "+f"(c[1]), "+f"(c[2]), "+f"(c[3])
        : "r"(a[0]), "r"(a[1]), "r"(a[2]), "r"(a[3]), "r"(b[0]), "r"(b[1]));
}
// fp32 bits fed directly as tf32 (HW truncates low mantissa bits)
__device__ __forceinline__ uint32_t asbits(float f) { return __float_as_uint(f); }

// ---------------- K1: v2 = W2 @ w_deep, c = b2 . w_deep ----------------
__global__ void k_prep(const float* __restrict__ W2,
                       const float* __restrict__ w_deep,
                       const float* __restrict__ b2) {
    int h = blockIdx.x * blockDim.x + threadIdx.x;
    if (h < HH) {
        float acc = 0.f;
        const float* row = W2 + (size_t)h * DOUTT;
#pragma unroll 8
        for (int d = 0; d < DOUTT; d++) acc = fmaf(row[d], w_deep[d], acc);
        g_v2[h] = acc;
    }
    if (blockIdx.x == 0 && threadIdx.x == 0) {
        float c = 0.f;
        for (int d = 0; d < DOUTT; d++) c = fmaf(b2[d], w_deep[d], c);
        g_c = c;
    }
}

// ---------------- K2: tf32 mma.sync MLP, fused u and y partials ----------------
// 256 threads = 8 warps (4m x 2n), warp tile 32x64, BM=128, BN=128,
// nc-loop over 8 chunks of 128 hidden cols, K=512 in 16 chunks of 32.
// Fragment double-buffer across the 4 ks steps hides LDS latency behind HMMA.
#define OFF_A0   0
#define OFF_A1   4608
#define OFF_B0   9216
#define OFF_B1   13568
#define OFF_B1S  17920
#define OFF_V2S  18944
#define OFF_RED  19968
#define OFF_US   20992
#define MLP_SMEM_BYTES ((20992 + 128) * 4)

__device__ __forceinline__ void mlp_load(uint32_t sb, uint32_t aoff, uint32_t boff,
                                         const float* __restrict__ d1,
                                         const float* __restrict__ W1,
                                         int mbase, int kbase, int nbase, int tid) {
#pragma unroll
    for (int c = 0; c < 4; c++) {
        int id = c * 256 + tid;
        int row = id >> 3, cc = id & 7;
        cp16(sb + (aoff + row * 36 + cc * 4) * 4,
             &d1[(size_t)(mbase + row) * DIN + kbase + cc * 4]);
    }
#pragma unroll
    for (int c = 0; c < 4; c++) {
        int id = c * 256 + tid;
        int row = id >> 5, cc = id & 31;
        cp16(sb + (boff + row * 136 + cc * 4) * 4,
             &W1[(size_t)(kbase + row) * HH + nbase + cc * 4]);
    }
}

__device__ __forceinline__ void load_frags(uint32_t af[2][4], uint32_t bf[8][2],
                                           const float* __restrict__ As,
                                           const float* __restrict__ Bs,
                                           int k0, int wm, int wn, int lq, int lr) {
#pragma unroll
    for (int mt = 0; mt < 2; mt++) {
        const float* ap = As + (wm * 32 + mt * 16 + lq) * 36 + k0 + lr;
        af[mt][0] = asbits(ap[0]);
        af[mt][1] = asbits(ap[8 * 36]);
        af[mt][2] = asbits(ap[4]);
        af[mt][3] = asbits(ap[8 * 36 + 4]);
    }
#pragma unroll
    for (int nt = 0; nt < 8; nt++) {
        const float* bp = Bs + (k0 + lr) * 136 + wn * 64 + nt * 8 + lq;
        bf[nt][0] = asbits(bp[0]);
        bf[nt][1] = asbits(bp[4 * 136]);
    }
}

__global__ __launch_bounds__(256)
void k_mlp(const float* __restrict__ d1, const float* __restrict__ W1,
           const float* __restrict__ b1, const float* __restrict__ S) {
    extern __shared__ float smf[];
    const uint32_t sb = smem_u32(smf);
    const int tid = threadIdx.x, wid = tid >> 5, lane = tid & 31;
    const int wm = wid >> 1, wn = wid & 1;       // warp grid 4 x 2
    const int mbase = blockIdx.x * 128;
    const int lq = lane >> 2, lr = lane & 3;

    float* b1s = smf + OFF_B1S;
    float* v2s = smf + OFF_V2S;
    for (int i = tid; i < HH; i += 256) { b1s[i] = b1[i]; v2s[i] = g_v2[i]; }
    __syncthreads();

    const uint32_t aoff[2] = {OFF_A0, OFF_A1};
    const uint32_t boff[2] = {OFF_B0, OFF_B1};
    float upart[4] = {0.f, 0.f, 0.f, 0.f};

    for (int nc = 0; nc < 8; nc++) {
        const int nbase = nc * 128;
        float c[2][8][4];
#pragma unroll
        for (int mt = 0; mt < 2; mt++)
#pragma unroll
            for (int nt = 0; nt < 8; nt++)
#pragma unroll
                for (int i = 0; i < 4; i++) c[mt][nt][i] = 0.f;

        mlp_load(sb, aoff[0], boff[0], d1, W1, mbase, 0, nbase, tid);
        CP_COMMIT();

        for (int kt = 0; kt < 16; kt++) {
            const int cur = kt & 1, nxt = cur ^ 1;
            CP_WAIT0();
            __syncthreads();
            if (kt < 15) {
                mlp_load(sb, aoff[nxt], boff[nxt], d1, W1, mbase, (kt + 1) * 32, nbase, tid);
                CP_COMMIT();
            }
            const float* As = smf + aoff[cur];
            const float* Bs = smf + boff[cur];

            uint32_t af[2][2][4], bf[2][8][2];
            load_frags(af[0], bf[0], As, Bs, 0, wm, wn, lq, lr);
#pragma unroll
            for (int ks = 0; ks < 4; ks++) {
                const int cb = ks & 1, nb = cb ^ 1;
                if (ks < 3)
                    load_frags(af[nb], bf[nb], As, Bs, (ks + 1) * 8, wm, wn, lq, lr);
#pragma unroll
                for (int mt = 0; mt < 2; mt++)
#pragma unroll
                    for (int nt = 0; nt < 8; nt++)
                        mma_tf32(c[mt][nt], af[cb][mt], bf[cb][nt]);
            }
        }
        // fused epilogue: upart += relu(c + b1) . v2
#pragma unroll
        for (int mt = 0; mt < 2; mt++)
#pragma unroll
            for (int nt = 0; nt < 8; nt++) {
                const int col0 = nbase + wn * 64 + nt * 8 + 2 * lr;
                const float b1a = b1s[col0], b1b = b1s[col0 + 1];
                const float v2a = v2s[col0], v2b = v2s[col0 + 1];
                upart[mt * 2 + 0] = fmaf(fmaxf(c[mt][nt][0] + b1a, 0.f), v2a, upart[mt * 2 + 0]);
                upart[mt * 2 + 0] = fmaf(fmaxf(c[mt][nt][1] + b1b, 0.f), v2b, upart[mt * 2 + 0]);
                upart[mt * 2 + 1] = fmaf(fmaxf(c[mt][nt][2] + b1a, 0.f), v2a, upart[mt * 2 + 1]);
                upart[mt * 2 + 1] = fmaf(fmaxf(c[mt][nt][3] + b1b, 0.f), v2b, upart[mt * 2 + 1]);
            }
        __syncthreads();  // before next nc overwrites buffers
    }

    // reduce 8 column-partials per row (deterministic), store u, then y partial
    float* red = smf + OFF_RED;   // [128][8]
    float* us  = smf + OFF_US;    // [128]
#pragma unroll
    for (int mt = 0; mt < 2; mt++)
#pragma unroll
        for (int hh = 0; hh < 2; hh++) {
            const int row = wm * 32 + mt * 16 + hh * 8 + lq;
            red[row * 8 + wn * 4 + lr] = upart[mt * 2 + hh];
        }
    __syncthreads();
    if (tid < 128) {
        float s = 0.f;
#pragma unroll
        for (int t = 0; t < 8; t++) s += red[tid * 8 + t];
        const float u = s + g_c;
        g_u[mbase + tid] = u;
        us[tid] = u;
    }
    __syncthreads();
    if (tid < 128) {
        float acc = 0.f;
#pragma unroll 8
        for (int r = 0; r < 128; r++)
            acc = fmaf(S[(size_t)(mbase + r) * SS + tid], us[r], acc);
        g_y_part[blockIdx.x * 128 + tid] = acc;
    }
}

// ---------------- K3: Gram partials (FFMA, known good) ----------------
__global__ __launch_bounds__(256) void k_gram(const float* __restrict__ Smat) {
    __shared__ __align__(16) float Srow[8][128];
    const int tid = threadIdx.x;
    const int tx = tid & 15, ty = tid >> 4;
    const int i0 = ty * 8, j0 = tx * 8;
    const int base = blockIdx.x * 512;
    const int lr = tid >> 5;
    const int lc = (tid & 31) * 4;

    float acc[8][8];
#pragma unroll
    for (int i = 0; i < 8; i++)
#pragma unroll
        for (int j = 0; j < 8; j++) acc[i][j] = 0.f;

    for (int st = 0; st < 64; st++) {
        __syncthreads();
        *(float4*)&Srow[lr][lc] = *(const float4*)&Smat[(size_t)(base + st * 8 + lr) * SS + lc];
        __syncthreads();
#pragma unroll
        for (int r = 0; r < 8; r++) {
            float a[8], b[8];
            *(float4*)&a[0] = *(float4*)&Srow[r][i0];
            *(float4*)&a[4] = *(float4*)&Srow[r][i0 + 4];
            *(float4*)&b[0] = *(float4*)&Srow[r][j0];
            *(float4*)&b[4] = *(float4*)&Srow[r][j0 + 4];
#pragma unroll
            for (int i = 0; i < 8; i++)
#pragma unroll
                for (int j = 0; j < 8; j++)
                    acc[i][j] = fmaf(a[i], b[j], acc[i][j]);
        }
    }
    float* outp = g_gram_part + (size_t)blockIdx.x * 128 * 128;
#pragma unroll
    for (int i = 0; i < 8; i++)
#pragma unroll
        for (int j = 0; j < 8; j++)
            outp[(i0 + i) * 128 + (j0 + j)] = acc[i][j];
}

// ---------------- K4: reduce partials (deterministic fixed order) ----------------
__global__ void k_reduce() {
    const int idx = blockIdx.x * blockDim.x + threadIdx.x;
    if (idx < 128 * 128) {
        float s = 0.f;
        for (int b = 0; b < 128; b++) s += g_gram_part[(size_t)b * 16384 + idx];
        g_G[idx] = s;
    }
    if (idx < 128) {
        float s = 0.f;
        for (int b = 0; b < 512; b++) s += g_y_part[b * 128 + idx];
        g_y[idx] = s;
    }
}

// ---------------- K5: Richardson solve G z = y ----------------
__global__ void k_solve(const float* __restrict__ w_struct) {
    __shared__ float zs[128];
    const int i = threadIdx.x;
    const float invN = 1.0f / (float)NN;
    const float yi = g_y[i];
    zs[i] = yi * invN;
    __syncthreads();
    for (int it = 0; it < 30; it++) {
        float gz = 0.f;
        const float* Gi = g_G + i * 128;
#pragma unroll 8
        for (int j = 0; j < 128; j++) gz = fmaf(Gi[j], zs[j], gz);
        const float znew = zs[i] + (yi - gz) * invN;
        __syncthreads();
        zs[i] = znew;
        __syncthreads();
    }
    g_wprime[i] = w_struct[i] - zs[i];
}

// ---------------- K6: out[n] = u[n] + S[n,:] . wprime ----------------
__global__ __launch_bounds__(256) void k_final(const float* __restrict__ Smat,
                                               float* __restrict__ out) {
    __shared__ float wp[128];
    const int tid = threadIdx.x;
    if (tid < 128) wp[tid] = g_wprime[tid];
    __syncthreads();
    const int warp = tid >> 5, lane = tid & 31;
    const int row = blockIdx.x * 8 + warp;
    const float4 a = *(const float4*)&Smat[(size_t)row * SS + lane * 4];
    const float4 w = *(const float4*)&wp[lane * 4];
    float s = a.x * w.x + a.y * w.y + a.z * w.z + a.w * w.w;
#pragma unroll
    for (int off = 16; off; off >>= 1) s += __shfl_xor_sync(0xffffffffu, s, off);
    if (lane == 0) out[row] = g_u[row] + s;
}

// ---------------- launch ----------------
extern "C" void kernel_launch(void* const* d_in, const int* in_sizes, int n_in,
                              void* d_out, int out_size) {
    const float* structured = (const float*)d_in[0];
    const float* d1         = (const float*)d_in[1];
    const float* W1         = (const float*)d_in[2];
    const float* b1         = (const float*)d_in[3];
    const float* W2         = (const float*)d_in[4];
    const float* b2         = (const float*)d_in[5];
    const float* w_struct   = (const float*)d_in[6];
    const float* w_deep     = (const float*)d_in[7];
    float* out = (float*)d_out;
    (void)in_sizes; (void)n_in; (void)out_size;

    cudaFuncSetAttribute(k_mlp, cudaFuncAttributeMaxDynamicSharedMemorySize, MLP_SMEM_BYTES);

    k_prep  <<<4, 256>>>(W2, w_deep, b2);
    k_mlp   <<<NN / 128, 256, MLP_SMEM_BYTES>>>(d1, W1, b1, structured);
    k_gram  <<<128, 256>>>(structured);
    k_reduce<<<64, 256>>>();
    k_solve <<<1, 128>>>(w_struct);
    k_final <<<NN / 8, 256>>>(structured, out);
}

// round 7
// speedup vs baseline: 1.6129x; 1.0140x over previous
#include <cuda_runtime.h>
#include <cuda_bf16.h>
#include <cstdint>

#define NN   65536
#define SS   128
#define DIN  512
#define HH   1024
#define DOUTT 256

// ---------------- static device scratch ----------------
__device__ float g_u[NN];
__device__ float g_v2[HH];
__device__ float g_c;
__device__ float g_gram_part[128 * 128 * 128];
__device__ float g_y_part[512 * 128];
__device__ float g_G[128 * 128];
__device__ float g_y[128];
__device__ float g_wprime[128];

// ---------------- helpers (baseline PTX only — must compile for plain sm_103) ----------------
__device__ __forceinline__ uint32_t smem_u32(const void* p) {
    uint32_t a;
    asm("{ .reg .u64 t; cvta.to.shared.u64 t, %1; cvt.u32.u64 %0, t; }" : "=r"(a) : "l"(p));
    return a;
}
__device__ __forceinline__ void cp16(uint32_t dst, const void* src) {
    asm volatile("cp.async.cg.shared.global [%0], [%1], 16;" :: "r"(dst), "l"(src));
}
#define CP_COMMIT() asm volatile("cp.async.commit_group;" ::: "memory")
#define CP_WAIT0()  asm volatile("cp.async.wait_group 0;" ::: "memory")

__device__ __forceinline__ void mma_tf32(float* c, const uint32_t* a, const uint32_t* b) {
    asm volatile("mma.sync.aligned.m16n8k8.row.col.f32.tf32.tf32.f32 "
        "{%0,%1,%2,%3}, {%4,%5,%6,%7}, {%8,%9}, {%0,%1,%2,%3};"
        : "+f"(c[0]), "+f"(c[1]), "+f"(c[2]), "+f"(c[3])
        : "r"(a[0]), "r"(a[1]), "r"(a[2]), "r"(a[3]), "r"(b[0]), "r"(b[1]));
}
// fp32 bits fed directly as tf32 (HW truncates low mantissa bits)
__device__ __forceinline__ uint32_t asbits(float f) { return __float_as_uint(f); }

// ---------------- K1: v2 = W2 @ w_deep, c = b2 . w_deep ----------------
__global__ void k_prep(const float* __restrict__ W2,
                       const float* __restrict__ w_deep,
                       const float* __restrict__ b2) {
    int h = blockIdx.x * blockDim.x + threadIdx.x;
    if (h < HH) {
        float acc = 0.f;
        const float* row = W2 + (size_t)h * DOUTT;
#pragma unroll 8
        for (int d = 0; d < DOUTT; d++) acc = fmaf(row[d], w_deep[d], acc);
        g_v2[h] = acc;
    }
    if (blockIdx.x == 0 && threadIdx.x == 0) {
        float c = 0.f;
        for (int d = 0; d < DOUTT; d++) c = fmaf(b2[d], w_deep[d], c);
        g_c = c;
    }
}

// ---------------- K2: tf32 mma.sync MLP, fused u and y partials ----------------
// 256 threads = 8 warps (4m x 2n), warp tile 32x64, BM=128, BN=128, KC=16.
// Smem ~50 KB -> 2 CTAs/SM -> 4 warps/SMSP for latency cover.
// SMEM float offsets (padded strides: A row = 20 floats, B row = 136 floats)
#define OFF_A0   0
#define OFF_A1   2560
#define OFF_B0   5120
#define OFF_B1   7296
#define OFF_B1S  9472
#define OFF_V2S  10496
#define OFF_RED  11520
#define OFF_US   12544
#define MLP_SMEM_BYTES ((12544 + 160) * 4)

__device__ __forceinline__ void mlp_load(uint32_t sb, uint32_t aoff, uint32_t boff,
                                         const float* __restrict__ d1,
                                         const float* __restrict__ W1,
                                         int mbase, int kbase, int nbase, int tid) {
    // A: 128 rows x 16 floats = 512 16B chunks -> 2/thread
#pragma unroll
    for (int c = 0; c < 2; c++) {
        int id = c * 256 + tid;
        int row = id >> 2, cc = id & 3;
        cp16(sb + (aoff + row * 20 + cc * 4) * 4,
             &d1[(size_t)(mbase + row) * DIN + kbase + cc * 4]);
    }
    // B: 16 rows x 128 floats = 512 chunks -> 2/thread
#pragma unroll
    for (int c = 0; c < 2; c++) {
        int id = c * 256 + tid;
        int row = id >> 5, cc = id & 31;
        cp16(sb + (boff + row * 136 + cc * 4) * 4,
             &W1[(size_t)(kbase + row) * HH + nbase + cc * 4]);
    }
}

__global__ __launch_bounds__(256, 2)
void k_mlp(const float* __restrict__ d1, const float* __restrict__ W1,
           const float* __restrict__ b1, const float* __restrict__ S) {
    extern __shared__ float smf[];
    const uint32_t sb = smem_u32(smf);
    const int tid = threadIdx.x, wid = tid >> 5, lane = tid & 31;
    const int wm = wid >> 1, wn = wid & 1;       // warp grid 4 x 2
    const int mbase = blockIdx.x * 128;
    const int lq = lane >> 2, lr = lane & 3;

    float* b1s = smf + OFF_B1S;
    float* v2s = smf + OFF_V2S;
    for (int i = tid; i < HH; i += 256) { b1s[i] = b1[i]; v2s[i] = g_v2[i]; }
    __syncthreads();

    const uint32_t aoff[2] = {OFF_A0, OFF_A1};
    const uint32_t boff[2] = {OFF_B0, OFF_B1};
    float upart[4] = {0.f, 0.f, 0.f, 0.f};

    for (int nc = 0; nc < 8; nc++) {
        const int nbase = nc * 128;
        float c[2][8][4];
#pragma unroll
        for (int mt = 0; mt < 2; mt++)
#pragma unroll
            for (int nt = 0; nt < 8; nt++)
#pragma unroll
                for (int i = 0; i < 4; i++) c[mt][nt][i] = 0.f;

        mlp_load(sb, aoff[0], boff[0], d1, W1, mbase, 0, nbase, tid);
        CP_COMMIT();

        for (int kt = 0; kt < 32; kt++) {
            const int cur = kt & 1, nxt = cur ^ 1;
            CP_WAIT0();
            __syncthreads();
            if (kt < 31) {
                mlp_load(sb, aoff[nxt], boff[nxt], d1, W1, mbase, (kt + 1) * 16, nbase, tid);
                CP_COMMIT();
            }
            const float* As = smf + aoff[cur];
            const float* Bs = smf + boff[cur];
#pragma unroll
            for (int ks = 0; ks < 2; ks++) {
                const int k0 = ks * 8;
                uint32_t af[2][4];
#pragma unroll
                for (int mt = 0; mt < 2; mt++) {
                    const float* ap = As + (wm * 32 + mt * 16 + lq) * 20 + k0 + lr;
                    af[mt][0] = asbits(ap[0]);
                    af[mt][1] = asbits(ap[8 * 20]);
                    af[mt][2] = asbits(ap[4]);
                    af[mt][3] = asbits(ap[8 * 20 + 4]);
                }
                uint32_t bf[8][2];
#pragma unroll
                for (int nt = 0; nt < 8; nt++) {
                    const float* bp = Bs + (k0 + lr) * 136 + wn * 64 + nt * 8 + lq;
                    bf[nt][0] = asbits(bp[0]);
                    bf[nt][1] = asbits(bp[4 * 136]);
                }
#pragma unroll
                for (int mt = 0; mt < 2; mt++)
#pragma unroll
                    for (int nt = 0; nt < 8; nt++)
                        mma_tf32(c[mt][nt], af[mt], bf[nt]);
            }
        }
        // fused epilogue: upart += relu(c + b1) . v2
#pragma unroll
        for (int mt = 0; mt < 2; mt++)
#pragma unroll
            for (int nt = 0; nt < 8; nt++) {
                const int col0 = nbase + wn * 64 + nt * 8 + 2 * lr;
                const float b1a = b1s[col0], b1b = b1s[col0 + 1];
                const float v2a = v2s[col0], v2b = v2s[col0 + 1];
                upart[mt * 2 + 0] = fmaf(fmaxf(c[mt][nt][0] + b1a, 0.f), v2a, upart[mt * 2 + 0]);
                upart[mt * 2 + 0] = fmaf(fmaxf(c[mt][nt][1] + b1b, 0.f), v2b, upart[mt * 2 + 0]);
                upart[mt * 2 + 1] = fmaf(fmaxf(c[mt][nt][2] + b1a, 0.f), v2a, upart[mt * 2 + 1]);
                upart[mt * 2 + 1] = fmaf(fmaxf(c[mt][nt][3] + b1b, 0.f), v2b, upart[mt * 2 + 1]);
            }
        __syncthreads();  // before next nc overwrites buffers
    }

    // reduce 8 column-partials per row (deterministic), store u, then y partial
    float* red = smf + OFF_RED;   // [128][8]
    float* us  = smf + OFF_US;    // [128]
#pragma unroll
    for (int mt = 0; mt < 2; mt++)
#pragma unroll
        for (int hh = 0; hh < 2; hh++) {
            const int row = wm * 32 + mt * 16 + hh * 8 + lq;
            red[row * 8 + wn * 4 + lr] = upart[mt * 2 + hh];
        }
    __syncthreads();
    if (tid < 128) {
        float s = 0.f;
#pragma unroll
        for (int t = 0; t < 8; t++) s += red[tid * 8 + t];
        const float u = s + g_c;
        g_u[mbase + tid] = u;
        us[tid] = u;
    }
    __syncthreads();
    if (tid < 128) {
        float acc = 0.f;
#pragma unroll 8
        for (int r = 0; r < 128; r++)
            acc = fmaf(S[(size_t)(mbase + r) * SS + tid], us[r], acc);
        g_y_part[blockIdx.x * 128 + tid] = acc;
    }
}

// ---------------- K3: Gram partials (FFMA, known good) ----------------
__global__ __launch_bounds__(256) void k_gram(const float* __restrict__ Smat) {
    __shared__ __align__(16) float Srow[8][128];
    const int tid = threadIdx.x;
    const int tx = tid & 15, ty = tid >> 4;
    const int i0 = ty * 8, j0 = tx * 8;
    const int base = blockIdx.x * 512;
    const int lr = tid >> 5;
    const int lc = (tid & 31) * 4;

    float acc[8][8];
#pragma unroll
    for (int i = 0; i < 8; i++)
#pragma unroll
        for (int j = 0; j < 8; j++) acc[i][j] = 0.f;

    for (int st = 0; st < 64; st++) {
        __syncthreads();
        *(float4*)&Srow[lr][lc] = *(const float4*)&Smat[(size_t)(base + st * 8 + lr) * SS + lc];
        __syncthreads();
#pragma unroll
        for (int r = 0; r < 8; r++) {
            float a[8], b[8];
            *(float4*)&a[0] = *(float4*)&Srow[r][i0];
            *(float4*)&a[4] = *(float4*)&Srow[r][i0 + 4];
            *(float4*)&b[0] = *(float4*)&Srow[r][j0];
            *(float4*)&b[4] = *(float4*)&Srow[r][j0 + 4];
#pragma unroll
            for (int i = 0; i < 8; i++)
#pragma unroll
                for (int j = 0; j < 8; j++)
                    acc[i][j] = fmaf(a[i], b[j], acc[i][j]);
        }
    }
    float* outp = g_gram_part + (size_t)blockIdx.x * 128 * 128;
#pragma unroll
    for (int i = 0; i < 8; i++)
#pragma unroll
        for (int j = 0; j < 8; j++)
            outp[(i0 + i) * 128 + (j0 + j)] = acc[i][j];
}

// ---------------- K4: reduce partials, 4 threads per output (fixed-order tree) ----------------
__global__ __launch_bounds__(256) void k_reduce() {
    __shared__ float p[256];
    const int tid = threadIdx.x;
    const int il = tid >> 2;            // 0..63 local output index
    const int part = tid & 3;           // 0..3
    const int idx = blockIdx.x * 64 + il;

    // Gram: 128 partials -> 4 chunks of 32, combined in fixed order
    {
        float s = 0.f;
        const int b0 = part * 32;
        for (int b = 0; b < 32; b++)
            s += g_gram_part[(size_t)(b0 + b) * 16384 + idx];
        p[tid] = s;
    }
    __syncthreads();
    if (part == 0)
        g_G[idx] = p[il * 4] + p[il * 4 + 1] + p[il * 4 + 2] + p[il * 4 + 3];

    // y: 512 partials, only block 0's first 128 outputs
    if (blockIdx.x == 0 && tid < 128) {
        // handled by 128 threads, serial but short; separate from Gram path
    }
    __syncthreads();
    if (blockIdx.x == 0) {
        const int j = tid >> 1;         // 0..127
        const int half = tid & 1;       // 0..1
        float s = 0.f;
        const int b0 = half * 256;
        for (int b = 0; b < 256; b++)
            s += g_y_part[(b0 + b) * 128 + j];
        p[tid] = s;
        __syncthreads();
        if (half == 0) g_y[j] = p[j * 2] + p[j * 2 + 1];
    }
}

// ---------------- K5: Richardson solve G z = y ----------------
__global__ void k_solve(const float* __restrict__ w_struct) {
    __shared__ float zs[128];
    const int i = threadIdx.x;
    const float invN = 1.0f / (float)NN;
    const float yi = g_y[i];
    zs[i] = yi * invN;
    __syncthreads();
    for (int it = 0; it < 30; it++) {
        float gz = 0.f;
        const float* Gi = g_G + i * 128;
#pragma unroll 8
        for (int j = 0; j < 128; j++) gz = fmaf(Gi[j], zs[j], gz);
        const float znew = zs[i] + (yi - gz) * invN;
        __syncthreads();
        zs[i] = znew;
        __syncthreads();
    }
    g_wprime[i] = w_struct[i] - zs[i];
}

// ---------------- K6: out[n] = u[n] + S[n,:] . wprime ----------------
__global__ __launch_bounds__(256) void k_final(const float* __restrict__ Smat,
                                               float* __restrict__ out) {
    __shared__ float wp[128];
    const int tid = threadIdx.x;
    if (tid < 128) wp[tid] = g_wprime[tid];
    __syncthreads();
    const int warp = tid >> 5, lane = tid & 31;
    const int row = blockIdx.x * 8 + warp;
    const float4 a = *(const float4*)&Smat[(size_t)row * SS + lane * 4];
    const float4 w = *(const float4*)&wp[lane * 4];
    float s = a.x * w.x + a.y * w.y + a.z * w.z + a.w * w.w;
#pragma unroll
    for (int off = 16; off; off >>= 1) s += __shfl_xor_sync(0xffffffffu, s, off);
    if (lane == 0) out[row] = g_u[row] + s;
}

// ---------------- launch ----------------
extern "C" void kernel_launch(void* const* d_in, const int* in_sizes, int n_in,
                              void* d_out, int out_size) {
    const float* structured = (const float*)d_in[0];
    const float* d1         = (const float*)d_in[1];
    const float* W1         = (const float*)d_in[2];
    const float* b1         = (const float*)d_in[3];
    const float* W2         = (const float*)d_in[4];
    const float* b2         = (const float*)d_in[5];
    const float* w_struct   = (const float*)d_in[6];
    const float* w_deep     = (const float*)d_in[7];
    float* out = (float*)d_out;
    (void)in_sizes; (void)n_in; (void)out_size;

    cudaFuncSetAttribute(k_mlp, cudaFuncAttributeMaxDynamicSharedMemorySize, MLP_SMEM_BYTES);

    k_prep  <<<4, 256>>>(W2, w_deep, b2);
    k_mlp   <<<NN / 128, 256, MLP_SMEM_BYTES>>>(d1, W1, b1, structured);
    k_gram  <<<128, 256>>>(structured);
    k_reduce<<<256, 256>>>();
    k_solve <<<1, 128>>>(w_struct);
    k_final <<<NN / 8, 256>>>(structured, out);
}